// round 6
// baseline (speedup 1.0000x reference)
#include <cuda_runtime.h>
#include <cstdint>

#define B_IMG 16
#define HGT 1024
#define WID 1024
#define HW (1u << 20)
#define CAP (1 << 17)
#define NEG_INF __int_as_float(0xff800000)

// ---------------- scratch ----------------
__device__ float g_R[(size_t)B_IMG * HW];
__device__ int   g_RmaxBits[B_IMG];
__device__ int   g_count[B_IMG];
__device__ unsigned long long g_candKey[B_IMG][CAP];  // (valBits<<32)|(~idx)

__global__ void initK() {
    int t = threadIdx.x;
    if (t < B_IMG) { g_RmaxBits[t] = 0; g_count[t] = 0; }
}

__device__ __forceinline__ float4 ld4(const float* p) { return *(const float4*)p; }
__device__ __forceinline__ void st4(float* p, float4 v) { *(float4*)p = v; }

// 15-tap horizontal max for 4 adjacent outputs from 18 consecutive values
// common covers v3..v14 (includes B.w = v7)
__device__ __forceinline__ float4 hmax15(float4 A, float4 B, float4 C, float4 D, float4 E) {
    float common = fmaxf(fmaxf(fmaxf(fmaxf(A.w, B.x), fmaxf(B.y, B.z)), B.w),
                   fmaxf(fmaxf(fmaxf(C.x, C.y), fmaxf(C.z, C.w)),
                         fmaxf(D.x, fmaxf(D.y, D.z))));            // v3..v14
    float4 r;
    r.x = fmaxf(common, fmaxf(fmaxf(A.x, A.y), A.z));              // v0..v14
    r.y = fmaxf(common, fmaxf(fmaxf(A.y, A.z), D.w));              // v1..v15
    r.z = fmaxf(common, fmaxf(fmaxf(A.z, D.w), E.x));              // v2..v16
    r.w = fmaxf(common, fmaxf(fmaxf(D.w, E.x), E.y));              // v3..v17
    return r;
}

// ---------------- fused response kernel: 32 wide x 64 tall output tile ----------------
// H[r][c] (r=0..69) = 7-tap horizontal sum of gradient products at product-row
// py = Y0-3+r, centered at gx = X0+c. Output (ly,lx): Sxx = sum_{k=0..6} H[ly+k][lx].
__global__ void __launch_bounds__(256) computeR(const float* __restrict__ img) {
    const int b  = blockIdx.z;
    const int X0 = blockIdx.x * 32;
    const int Y0 = blockIdx.y * 64;

    __shared__ __align__(16) float S[72][40];                       // gy=Y0-4+r, gx=X0-4+c
    __shared__ __align__(16) float Hxx[70][32], Hyy[70][32], Hxy[70][32];
    __shared__ float warpMax[8];

    const float* im = img + (size_t)b * HW;
    const int tid = threadIdx.x;

    // phase 1: load + quantize image with 4-halo (72x40); zero outside
    for (int i = tid; i < 72 * 40; i += 256) {
        int r = i / 40, c = i % 40;
        int gy = Y0 - 4 + r, gx = X0 - 4 + c;
        float v = 0.0f;
        if (gy >= 0 && gy < HGT && gx >= 0 && gx < WID) {
            float t = im[gy * WID + gx];
            v = fminf(fmaxf(floorf(t * 255.0f), 0.0f), 255.0f) / 255.0f;
        }
        S[r][c] = v;
    }
    __syncthreads();

    // phase 2 (fused sobel + products + horizontal 7-sum): 70 rows x 8 chunks = 560 tasks
    for (int i = tid; i < 560; i += 256) {
        int r = i >> 3, c0 = (i & 7) << 2;
        float4 a0 = ld4(&S[r][c0]),     a1 = ld4(&S[r][c0 + 4]),     a2 = ld4(&S[r][c0 + 8]);
        float4 b0 = ld4(&S[r + 1][c0]), b1 = ld4(&S[r + 1][c0 + 4]), b2 = ld4(&S[r + 1][c0 + 8]);
        float4 d0 = ld4(&S[r + 2][c0]), d1 = ld4(&S[r + 2][c0 + 4]), d2 = ld4(&S[r + 2][c0 + 8]);
        float s0[12] = {a0.x,a0.y,a0.z,a0.w, a1.x,a1.y,a1.z,a1.w, a2.x,a2.y,a2.z,a2.w};
        float s1[12] = {b0.x,b0.y,b0.z,b0.w, b1.x,b1.y,b1.z,b1.w, b2.x,b2.y,b2.z,b2.w};
        float s2[12] = {d0.x,d0.y,d0.z,d0.w, d1.x,d1.y,d1.z,d1.w, d2.x,d2.y,d2.z,d2.w};
        int py = Y0 - 3 + r;
        float rowOK = (py >= 0 && py < HGT) ? 1.0f : 0.0f;
        float pxx[10], pyy[10], pxy[10];
#pragma unroll
        for (int j = 0; j < 10; j++) {
            int gx = X0 + c0 - 3 + j;
            float m = (gx >= 0 && gx < WID) ? rowOK : 0.0f;
            float ix = ((s0[j + 2] - s0[j])
                     + 2.0f * (s1[j + 2] - s1[j])
                     + (s2[j + 2] - s2[j])) * m;
            float iy = ((s2[j] + 2.0f * s2[j + 1] + s2[j + 2])
                     - (s0[j] + 2.0f * s0[j + 1] + s0[j + 2])) * m;
            pxx[j] = ix * ix; pyy[j] = iy * iy; pxy[j] = ix * iy;
        }
        float cxx = (pxx[3] + pxx[4]) + (pxx[5] + pxx[6]);
        float cyy = (pyy[3] + pyy[4]) + (pyy[5] + pyy[6]);
        float cxy = (pxy[3] + pxy[4]) + (pxy[5] + pxy[6]);
        st4(&Hxx[r][c0], make_float4(((pxx[0]+pxx[1])+pxx[2])+cxx,
                                     (pxx[1]+pxx[2])+cxx+pxx[7],
                                     pxx[2]+cxx+(pxx[7]+pxx[8]),
                                     cxx+((pxx[7]+pxx[8])+pxx[9])));
        st4(&Hyy[r][c0], make_float4(((pyy[0]+pyy[1])+pyy[2])+cyy,
                                     (pyy[1]+pyy[2])+cyy+pyy[7],
                                     pyy[2]+cyy+(pyy[7]+pyy[8]),
                                     cyy+((pyy[7]+pyy[8])+pyy[9])));
        st4(&Hxy[r][c0], make_float4(((pxy[0]+pxy[1])+pxy[2])+cxy,
                                     (pxy[1]+pxy[2])+cxy+pxy[7],
                                     pxy[2]+cxy+(pxy[7]+pxy[8]),
                                     cxy+((pxy[7]+pxy[8])+pxy[9])));
    }
    __syncthreads();

    // phase 3: vertical 7-sum for 2 consecutive rows per thread (shared 6-row mid)
    float localMax = 0.0f;
    {
        int c0 = (tid & 7) << 2, ly = (tid >> 3) << 1;
        float4 rxx[8], ryy[8], rxy[8];
#pragma unroll
        for (int k = 0; k < 8; k++) {
            rxx[k] = ld4(&Hxx[ly + k][c0]);
            ryy[k] = ld4(&Hyy[ly + k][c0]);
            rxy[k] = ld4(&Hxy[ly + k][c0]);
        }
        float4 mxx = rxx[1], myy = ryy[1], mxy = rxy[1];
#pragma unroll
        for (int k = 2; k < 7; k++) {
            mxx.x += rxx[k].x; mxx.y += rxx[k].y; mxx.z += rxx[k].z; mxx.w += rxx[k].w;
            myy.x += ryy[k].x; myy.y += ryy[k].y; myy.z += ryy[k].z; myy.w += ryy[k].w;
            mxy.x += rxy[k].x; mxy.y += rxy[k].y; mxy.z += rxy[k].z; mxy.w += rxy[k].w;
        }
#pragma unroll
        for (int o = 0; o < 2; o++) {
            int e = (o == 0) ? 0 : 7;
            float4 sxx = mxx, syy = myy, sxy = mxy;
            sxx.x += rxx[e].x; sxx.y += rxx[e].y; sxx.z += rxx[e].z; sxx.w += rxx[e].w;
            syy.x += ryy[e].x; syy.y += ryy[e].y; syy.z += ryy[e].z; syy.w += ryy[e].w;
            sxy.x += rxy[e].x; sxy.y += rxy[e].y; sxy.z += rxy[e].z; sxy.w += rxy[e].w;
            float4 R;
            float ht = 0.5f * (sxx.x + syy.x), dd = 0.5f * (sxx.x - syy.x);
            R.x = ht - sqrtf(dd * dd + sxy.x * sxy.x);
            ht = 0.5f * (sxx.y + syy.y); dd = 0.5f * (sxx.y - syy.y);
            R.y = ht - sqrtf(dd * dd + sxy.y * sxy.y);
            ht = 0.5f * (sxx.z + syy.z); dd = 0.5f * (sxx.z - syy.z);
            R.z = ht - sqrtf(dd * dd + sxy.z * sxy.z);
            ht = 0.5f * (sxx.w + syy.w); dd = 0.5f * (sxx.w - syy.w);
            R.w = ht - sqrtf(dd * dd + sxy.w * sxy.w);
            *(float4*)&g_R[((size_t)b << 20) + (size_t)(Y0 + ly + o) * WID + (X0 + c0)] = R;
            localMax = fmaxf(localMax, fmaxf(fmaxf(R.x, R.y), fmaxf(R.z, R.w)));
        }
    }

#pragma unroll
    for (int o = 16; o > 0; o >>= 1)
        localMax = fmaxf(localMax, __shfl_xor_sync(0xffffffffu, localMax, o));
    if ((tid & 31) == 0) warpMax[tid >> 5] = localMax;
    __syncthreads();
    if (tid == 0) {
        float m = warpMax[0];
#pragma unroll
        for (int i = 1; i < 8; i++) m = fmaxf(m, warpMax[i]);
        atomicMax(&g_RmaxBits[b], __float_as_int(m));
    }
}

// ---------------- fused 15x15 NMS + threshold + collect: 32x64 tile ----------------
__global__ void __launch_bounds__(256) nmsCollect() {
    const int b  = blockIdx.z;
    const int X0 = blockIdx.x * 32;
    const int Y0 = blockIdx.y * 64;

    __shared__ __align__(16) float sh[78][48];   // gy=Y0-7+r, gx=X0-7+c; cols 46-47 pad
    __shared__ __align__(16) float hm[78][32];   // horizontal 15-max centered at gx=X0+c
    __shared__ float shThr;
    const int tid = threadIdx.x;
    const float* Rb = g_R + ((size_t)b << 20);

    for (int i = tid; i < 78 * 48; i += 256) {
        int r = i / 48, c = i % 48;
        int gy = Y0 - 7 + r, gx = X0 - 7 + c;
        sh[r][c] = (c < 46 && gy >= 0 && gy < HGT && gx >= 0 && gx < WID)
                   ? Rb[(size_t)gy * WID + gx] : NEG_INF;
    }
    if (tid == 0) shThr = 0.3f * __int_as_float(g_RmaxBits[b]);
    __syncthreads();

    // horizontal 15-max: 78 rows x 8 chunks = 624 tasks
    for (int i = tid; i < 624; i += 256) {
        int r = i >> 3, c0 = (i & 7) << 2;
        st4(&hm[r][c0], hmax15(ld4(&sh[r][c0]),      ld4(&sh[r][c0 + 4]),
                               ld4(&sh[r][c0 + 8]),  ld4(&sh[r][c0 + 12]),
                               ld4(&sh[r][c0 + 16])));
    }
    __syncthreads();

    // vertical 15-max for 2 consecutive rows per thread (shared 14-row mid)
    const float thr = shThr;
    {
        int c0 = (tid & 7) << 2, ly = (tid >> 3) << 1;
        float4 row0 = ld4(&hm[ly][c0]);
        float4 mid  = ld4(&hm[ly + 1][c0]);
#pragma unroll
        for (int k = 2; k < 15; k++) {
            float4 t = ld4(&hm[ly + k][c0]);
            mid.x = fmaxf(mid.x, t.x); mid.y = fmaxf(mid.y, t.y);
            mid.z = fmaxf(mid.z, t.z); mid.w = fmaxf(mid.w, t.w);
        }
        float4 row15 = ld4(&hm[ly + 15][c0]);
        float pool[2][4] = {
            { fmaxf(mid.x, row0.x),  fmaxf(mid.y, row0.y),
              fmaxf(mid.z, row0.z),  fmaxf(mid.w, row0.w) },
            { fmaxf(mid.x, row15.x), fmaxf(mid.y, row15.y),
              fmaxf(mid.z, row15.z), fmaxf(mid.w, row15.w) } };
#pragma unroll
        for (int o = 0; o < 2; o++) {
            int y = Y0 + ly + o;
            const float* cenRow = &sh[ly + o + 7][c0 + 7];
#pragma unroll
            for (int j = 0; j < 4; j++) {
                float rv = cenRow[j];
                if (rv >= pool[o][j] && rv >= thr) {
                    unsigned int idx = (unsigned int)(y * WID + (X0 + c0 + j));
                    int pos = atomicAdd(&g_count[b], 1);
                    if (pos < CAP)
                        g_candKey[b][pos] = ((unsigned long long)__float_as_uint(rv) << 32)
                                          | (unsigned long long)(0xFFFFFFFFu - idx);
                }
            }
        }
    }
}

// ---------------- exact per-image top-K: MSD radix select, parallel scan, early exit ----------------
__global__ void __launch_bounds__(512) selectK(float* __restrict__ out, const int* __restrict__ topkPtr) {
    const int b   = blockIdx.x;
    const int tid = threadIdx.x;
    const int topK = *topkPtr;
    int n = g_count[b]; if (n > CAP) n = CAP;

    __shared__ int hist[256];
    __shared__ int suf[256];
    __shared__ unsigned long long shK;
    __shared__ int shRem, shDone;

    if (tid == 0) { shK = 0ull; shRem = topK; shDone = (n <= topK) ? 1 : 0; }
    __syncthreads();

    for (int byte = 7; byte >= 0; byte--) {
        if (shDone) break;
        if (tid < 256) hist[tid] = 0;
        __syncthreads();
        const unsigned long long pref = shK;
        const int shift = byte * 8;
        for (int i = tid; i < n; i += 512) {
            unsigned long long key = g_candKey[b][i];
            bool match = (byte == 7) || ((key >> (shift + 8)) == (pref >> (shift + 8)));
            if (match) atomicAdd(&hist[(int)((key >> shift) & 255)], 1);
        }
        __syncthreads();
        if (tid < 256) suf[tid] = hist[tid];
        __syncthreads();
        for (int off = 1; off < 256; off <<= 1) {
            int v = 0;
            if (tid < 256 && tid + off < 256) v = suf[tid + off];
            __syncthreads();
            if (tid < 256) suf[tid] += v;
            __syncthreads();
        }
        if (tid < 256) {
            int rem   = shRem;
            int here  = suf[tid];
            int above = (tid < 255) ? suf[tid + 1] : 0;
            if (here >= rem && above < rem) {
                int inBin = rem - above;
                int cnt   = here - above;
                shK = pref | ((unsigned long long)(unsigned int)tid << shift);
                if (inBin == cnt || byte == 0) shDone = 1;
                else shRem = inBin;
            }
        }
        __syncthreads();
    }

    const unsigned long long K = (n <= topK) ? 0ull : shK;
    for (int i = tid; i < n; i += 512) {
        unsigned long long key = g_candKey[b][i];
        if (key >= K) {
            unsigned int idx = 0xFFFFFFFFu - (unsigned int)(key & 0xFFFFFFFFull);
            out[((size_t)b << 20) + idx] = 1.0f;
        }
    }
}

// ---------------- launch ----------------
extern "C" void kernel_launch(void* const* d_in, const int* in_sizes, int n_in,
                              void* d_out, int out_size) {
    const float* img  = (const float*)d_in[0];
    const int*   topk = (const int*)d_in[1];
    float*       out  = (float*)d_out;

    cudaMemsetAsync(d_out, 0, (size_t)out_size * sizeof(float), 0);
    initK<<<1, 32>>>();
    computeR<<<dim3(32, 16, B_IMG), 256>>>(img);
    nmsCollect<<<dim3(32, 16, B_IMG), 256>>>();
    selectK<<<B_IMG, 512>>>(out, topk);
}

// round 7
// speedup vs baseline: 1.3904x; 1.3904x over previous
#include <cuda_runtime.h>
#include <cstdint>

#define B_IMG 16
#define HGT 1024
#define WID 1024
#define HW (1u << 20)
#define CAP (1 << 17)
#define NEG_INF __int_as_float(0xff800000)

// ---------------- scratch ----------------
__device__ float g_R[(size_t)B_IMG * HW];
__device__ int   g_RmaxBits[B_IMG];
__device__ int   g_count[B_IMG];
__device__ unsigned long long g_candKey[B_IMG][CAP];  // (valBits<<32)|(~idx)

__global__ void initK() {
    int t = threadIdx.x;
    if (t < B_IMG) { g_RmaxBits[t] = 0; g_count[t] = 0; }
}

__device__ __forceinline__ float4 ld4(const float* p) { return *(const float4*)p; }
__device__ __forceinline__ void st4(float* p, float4 v) { *(float4*)p = v; }

// 7-tap horizontal box sum of p[0..9] -> 4 outputs (same grouping as R6)
__device__ __forceinline__ float4 hsum7arr(const float* p) {
    float c = (p[3] + p[4]) + (p[5] + p[6]);
    return make_float4(((p[0] + p[1]) + p[2]) + c,
                       (p[1] + p[2]) + c + p[7],
                       p[2] + c + (p[7] + p[8]),
                       c + ((p[7] + p[8]) + p[9]));
}

// vertical 7-sum for 2 consecutive rows from one tensor (low register footprint)
__device__ __forceinline__ void vsum7pair(const float (*H)[32], int ly, int c0,
                                          float4& o0, float4& o1) {
    float4 r0  = ld4(&H[ly][c0]);
    float4 mid = ld4(&H[ly + 1][c0]);
#pragma unroll
    for (int k = 2; k < 7; k++) {
        float4 t = ld4(&H[ly + k][c0]);
        mid.x += t.x; mid.y += t.y; mid.z += t.z; mid.w += t.w;
    }
    float4 r7 = ld4(&H[ly + 7][c0]);
    o0 = make_float4(mid.x + r0.x, mid.y + r0.y, mid.z + r0.z, mid.w + r0.w);
    o1 = make_float4(mid.x + r7.x, mid.y + r7.y, mid.z + r7.z, mid.w + r7.w);
}

// 15-tap horizontal max for 4 adjacent outputs from 18 consecutive values
__device__ __forceinline__ float4 hmax15(float4 A, float4 B, float4 C, float4 D, float4 E) {
    float common = fmaxf(fmaxf(fmaxf(fmaxf(A.w, B.x), fmaxf(B.y, B.z)), B.w),
                   fmaxf(fmaxf(fmaxf(C.x, C.y), fmaxf(C.z, C.w)),
                         fmaxf(D.x, fmaxf(D.y, D.z))));            // v3..v14
    float4 r;
    r.x = fmaxf(common, fmaxf(fmaxf(A.x, A.y), A.z));              // v0..v14
    r.y = fmaxf(common, fmaxf(fmaxf(A.y, A.z), D.w));              // v1..v15
    r.z = fmaxf(common, fmaxf(fmaxf(A.z, D.w), E.x));              // v2..v16
    r.w = fmaxf(common, fmaxf(fmaxf(D.w, E.x), E.y));              // v3..v17
    return r;
}

// ---------------- fused response kernel: 32 wide x 64 tall output tile ----------------
__global__ void __launch_bounds__(256) computeR(const float* __restrict__ img) {
    const int b  = blockIdx.z;
    const int X0 = blockIdx.x * 32;
    const int Y0 = blockIdx.y * 64;

    __shared__ __align__(16) float S[72][40];                       // gy=Y0-4+r, gx=X0-4+c
    __shared__ __align__(16) float Hxx[70][32], Hyy[70][32], Hxy[70][32];
    __shared__ float warpMax[8];

    const float* im = img + (size_t)b * HW;
    const int tid = threadIdx.x;

    // phase 1: load + quantize image with 4-halo (72x40); zero outside
    for (int i = tid; i < 72 * 40; i += 256) {
        int r = i / 40, c = i % 40;
        int gy = Y0 - 4 + r, gx = X0 - 4 + c;
        float v = 0.0f;
        if (gy >= 0 && gy < HGT && gx >= 0 && gx < WID) {
            float t = im[gy * WID + gx];
            v = fminf(fmaxf(floorf(t * 255.0f), 0.0f), 255.0f) / 255.0f;
        }
        S[r][c] = v;
    }
    __syncthreads();

    // phase 2 (fused sobel + products + horizontal 7-sum): 70 rows x 8 chunks = 560 tasks
    // Two-stage to bound live registers: (a) ix[10], iy[10]; (b) per-tensor product + hsum.
    for (int i = tid; i < 560; i += 256) {
        int r = i >> 3, c0 = (i & 7) << 2;
        float ix[10], iy[10];
        {
            float4 a0 = ld4(&S[r][c0]),     a1 = ld4(&S[r][c0 + 4]),     a2 = ld4(&S[r][c0 + 8]);
            float4 b0 = ld4(&S[r + 1][c0]), b1 = ld4(&S[r + 1][c0 + 4]), b2 = ld4(&S[r + 1][c0 + 8]);
            float4 d0 = ld4(&S[r + 2][c0]), d1 = ld4(&S[r + 2][c0 + 4]), d2 = ld4(&S[r + 2][c0 + 8]);
            float s0[12] = {a0.x,a0.y,a0.z,a0.w, a1.x,a1.y,a1.z,a1.w, a2.x,a2.y,a2.z,a2.w};
            float s1[12] = {b0.x,b0.y,b0.z,b0.w, b1.x,b1.y,b1.z,b1.w, b2.x,b2.y,b2.z,b2.w};
            float s2[12] = {d0.x,d0.y,d0.z,d0.w, d1.x,d1.y,d1.z,d1.w, d2.x,d2.y,d2.z,d2.w};
            int py = Y0 - 3 + r;
            float rowOK = (py >= 0 && py < HGT) ? 1.0f : 0.0f;
#pragma unroll
            for (int j = 0; j < 10; j++) {
                int gx = X0 + c0 - 3 + j;
                float m = (gx >= 0 && gx < WID) ? rowOK : 0.0f;
                ix[j] = ((s0[j + 2] - s0[j])
                       + 2.0f * (s1[j + 2] - s1[j])
                       + (s2[j + 2] - s2[j])) * m;
                iy[j] = ((s2[j] + 2.0f * s2[j + 1] + s2[j + 2])
                       - (s0[j] + 2.0f * s0[j + 1] + s0[j + 2])) * m;
            }
        }
        {
            float p[10];
#pragma unroll
            for (int j = 0; j < 10; j++) p[j] = ix[j] * ix[j];
            st4(&Hxx[r][c0], hsum7arr(p));
#pragma unroll
            for (int j = 0; j < 10; j++) p[j] = iy[j] * iy[j];
            st4(&Hyy[r][c0], hsum7arr(p));
#pragma unroll
            for (int j = 0; j < 10; j++) p[j] = ix[j] * iy[j];
            st4(&Hxy[r][c0], hsum7arr(p));
        }
    }
    __syncthreads();

    // phase 3: vertical 7-sum for 2 consecutive rows per thread, tensors processed
    // SEQUENTIALLY to keep live registers low (was 24 float4 at once in R6).
    float localMax = 0.0f;
    {
        int c0 = (tid & 7) << 2, ly = (tid >> 3) << 1;
        float4 sxx0, sxx1, syy0, syy1, sxy0, sxy1;
        vsum7pair(Hxx, ly, c0, sxx0, sxx1);
        vsum7pair(Hyy, ly, c0, syy0, syy1);
        vsum7pair(Hxy, ly, c0, sxy0, sxy1);
#pragma unroll
        for (int o = 0; o < 2; o++) {
            float4 sxx = o ? sxx1 : sxx0;
            float4 syy = o ? syy1 : syy0;
            float4 sxy = o ? sxy1 : sxy0;
            float4 R;
            float ht = 0.5f * (sxx.x + syy.x), dd = 0.5f * (sxx.x - syy.x);
            R.x = ht - sqrtf(dd * dd + sxy.x * sxy.x);
            ht = 0.5f * (sxx.y + syy.y); dd = 0.5f * (sxx.y - syy.y);
            R.y = ht - sqrtf(dd * dd + sxy.y * sxy.y);
            ht = 0.5f * (sxx.z + syy.z); dd = 0.5f * (sxx.z - syy.z);
            R.z = ht - sqrtf(dd * dd + sxy.z * sxy.z);
            ht = 0.5f * (sxx.w + syy.w); dd = 0.5f * (sxx.w - syy.w);
            R.w = ht - sqrtf(dd * dd + sxy.w * sxy.w);
            *(float4*)&g_R[((size_t)b << 20) + (size_t)(Y0 + ly + o) * WID + (X0 + c0)] = R;
            localMax = fmaxf(localMax, fmaxf(fmaxf(R.x, R.y), fmaxf(R.z, R.w)));
        }
    }

#pragma unroll
    for (int o = 16; o > 0; o >>= 1)
        localMax = fmaxf(localMax, __shfl_xor_sync(0xffffffffu, localMax, o));
    if ((tid & 31) == 0) warpMax[tid >> 5] = localMax;
    __syncthreads();
    if (tid == 0) {
        float m = warpMax[0];
#pragma unroll
        for (int i = 1; i < 8; i++) m = fmaxf(m, warpMax[i]);
        atomicMax(&g_RmaxBits[b], __float_as_int(m));
    }
}

// ---------------- fused 15x15 NMS + threshold + collect: 32x64 tile ----------------
__global__ void __launch_bounds__(256) nmsCollect() {
    const int b  = blockIdx.z;
    const int X0 = blockIdx.x * 32;
    const int Y0 = blockIdx.y * 64;

    __shared__ __align__(16) float sh[78][48];   // gy=Y0-7+r, gx=X0-7+c; cols 46-47 pad
    __shared__ __align__(16) float hm[78][32];   // horizontal 15-max centered at gx=X0+c
    __shared__ float shThr;
    const int tid = threadIdx.x;
    const float* Rb = g_R + ((size_t)b << 20);

    for (int i = tid; i < 78 * 48; i += 256) {
        int r = i / 48, c = i % 48;
        int gy = Y0 - 7 + r, gx = X0 - 7 + c;
        sh[r][c] = (c < 46 && gy >= 0 && gy < HGT && gx >= 0 && gx < WID)
                   ? Rb[(size_t)gy * WID + gx] : NEG_INF;
    }
    if (tid == 0) shThr = 0.3f * __int_as_float(g_RmaxBits[b]);
    __syncthreads();

    // horizontal 15-max: 78 rows x 8 chunks = 624 tasks
    for (int i = tid; i < 624; i += 256) {
        int r = i >> 3, c0 = (i & 7) << 2;
        st4(&hm[r][c0], hmax15(ld4(&sh[r][c0]),      ld4(&sh[r][c0 + 4]),
                               ld4(&sh[r][c0 + 8]),  ld4(&sh[r][c0 + 12]),
                               ld4(&sh[r][c0 + 16])));
    }
    __syncthreads();

    // vertical 15-max for 2 consecutive rows per thread (shared 14-row mid)
    const float thr = shThr;
    {
        int c0 = (tid & 7) << 2, ly = (tid >> 3) << 1;
        float4 row0 = ld4(&hm[ly][c0]);
        float4 mid  = ld4(&hm[ly + 1][c0]);
#pragma unroll
        for (int k = 2; k < 15; k++) {
            float4 t = ld4(&hm[ly + k][c0]);
            mid.x = fmaxf(mid.x, t.x); mid.y = fmaxf(mid.y, t.y);
            mid.z = fmaxf(mid.z, t.z); mid.w = fmaxf(mid.w, t.w);
        }
        float4 row15 = ld4(&hm[ly + 15][c0]);
        float pool[2][4] = {
            { fmaxf(mid.x, row0.x),  fmaxf(mid.y, row0.y),
              fmaxf(mid.z, row0.z),  fmaxf(mid.w, row0.w) },
            { fmaxf(mid.x, row15.x), fmaxf(mid.y, row15.y),
              fmaxf(mid.z, row15.z), fmaxf(mid.w, row15.w) } };
#pragma unroll
        for (int o = 0; o < 2; o++) {
            int y = Y0 + ly + o;
            const float* cenRow = &sh[ly + o + 7][c0 + 7];
#pragma unroll
            for (int j = 0; j < 4; j++) {
                float rv = cenRow[j];
                if (rv >= pool[o][j] && rv >= thr) {
                    unsigned int idx = (unsigned int)(y * WID + (X0 + c0 + j));
                    int pos = atomicAdd(&g_count[b], 1);
                    if (pos < CAP)
                        g_candKey[b][pos] = ((unsigned long long)__float_as_uint(rv) << 32)
                                          | (unsigned long long)(0xFFFFFFFFu - idx);
                }
            }
        }
    }
}

// ---------------- exact per-image top-K: MSD radix select ----------------
__global__ void __launch_bounds__(512) selectK(float* __restrict__ out, const int* __restrict__ topkPtr) {
    const int b   = blockIdx.x;
    const int tid = threadIdx.x;
    const int topK = *topkPtr;
    int n = g_count[b]; if (n > CAP) n = CAP;

    __shared__ int hist[256];
    __shared__ int suf[256];
    __shared__ unsigned long long shK;
    __shared__ int shRem, shDone;

    if (tid == 0) { shK = 0ull; shRem = topK; shDone = (n <= topK) ? 1 : 0; }
    __syncthreads();

    for (int byte = 7; byte >= 0; byte--) {
        if (shDone) break;
        if (tid < 256) hist[tid] = 0;
        __syncthreads();
        const unsigned long long pref = shK;
        const int shift = byte * 8;
        for (int i = tid; i < n; i += 512) {
            unsigned long long key = g_candKey[b][i];
            bool match = (byte == 7) || ((key >> (shift + 8)) == (pref >> (shift + 8)));
            if (match) atomicAdd(&hist[(int)((key >> shift) & 255)], 1);
        }
        __syncthreads();
        if (tid < 256) suf[tid] = hist[tid];
        __syncthreads();
        for (int off = 1; off < 256; off <<= 1) {
            int v = 0;
            if (tid < 256 && tid + off < 256) v = suf[tid + off];
            __syncthreads();
            if (tid < 256) suf[tid] += v;
            __syncthreads();
        }
        if (tid < 256) {
            int rem   = shRem;
            int here  = suf[tid];
            int above = (tid < 255) ? suf[tid + 1] : 0;
            if (here >= rem && above < rem) {
                int inBin = rem - above;
                int cnt   = here - above;
                shK = pref | ((unsigned long long)(unsigned int)tid << shift);
                if (inBin == cnt || byte == 0) shDone = 1;
                else shRem = inBin;
            }
        }
        __syncthreads();
    }

    const unsigned long long K = (n <= topK) ? 0ull : shK;
    for (int i = tid; i < n; i += 512) {
        unsigned long long key = g_candKey[b][i];
        if (key >= K) {
            unsigned int idx = 0xFFFFFFFFu - (unsigned int)(key & 0xFFFFFFFFull);
            out[((size_t)b << 20) + idx] = 1.0f;
        }
    }
}

// ---------------- launch ----------------
extern "C" void kernel_launch(void* const* d_in, const int* in_sizes, int n_in,
                              void* d_out, int out_size) {
    const float* img  = (const float*)d_in[0];
    const int*   topk = (const int*)d_in[1];
    float*       out  = (float*)d_out;

    cudaMemsetAsync(d_out, 0, (size_t)out_size * sizeof(float), 0);
    initK<<<1, 32>>>();
    computeR<<<dim3(32, 16, B_IMG), 256>>>(img);
    nmsCollect<<<dim3(32, 16, B_IMG), 256>>>();
    selectK<<<B_IMG, 512>>>(out, topk);
}

// round 8
// speedup vs baseline: 1.4003x; 1.0072x over previous
#include <cuda_runtime.h>
#include <cstdint>

#define B_IMG 16
#define HGT 1024
#define WID 1024
#define HW (1u << 20)
#define CAP (1 << 17)
#define NEG_INF __int_as_float(0xff800000)

// ---------------- scratch ----------------
__device__ float g_R[(size_t)B_IMG * HW];
__device__ int   g_RmaxBits[B_IMG];
__device__ int   g_count[B_IMG];
__device__ unsigned long long g_candKey[B_IMG][CAP];  // (valBits<<32)|(~idx)

__global__ void initK() {
    int t = threadIdx.x;
    if (t < B_IMG) { g_RmaxBits[t] = 0; g_count[t] = 0; }
}

__device__ __forceinline__ float4 ld4(const float* p) { return *(const float4*)p; }
__device__ __forceinline__ void st4(float* p, float4 v) { *(float4*)p = v; }

// 7-tap horizontal box sum of p[0..9] -> 4 outputs
__device__ __forceinline__ float4 hsum7arr(const float* p) {
    float c = (p[3] + p[4]) + (p[5] + p[6]);
    return make_float4(((p[0] + p[1]) + p[2]) + c,
                       (p[1] + p[2]) + c + p[7],
                       p[2] + c + (p[7] + p[8]),
                       c + ((p[7] + p[8]) + p[9]));
}

// vertical 7-sum for 2 consecutive rows from one tensor (low register footprint)
__device__ __forceinline__ void vsum7pair(const float (*H)[32], int ly, int c0,
                                          float4& o0, float4& o1) {
    float4 r0  = ld4(&H[ly][c0]);
    float4 mid = ld4(&H[ly + 1][c0]);
#pragma unroll
    for (int k = 2; k < 7; k++) {
        float4 t = ld4(&H[ly + k][c0]);
        mid.x += t.x; mid.y += t.y; mid.z += t.z; mid.w += t.w;
    }
    float4 r7 = ld4(&H[ly + 7][c0]);
    o0 = make_float4(mid.x + r0.x, mid.y + r0.y, mid.z + r0.z, mid.w + r0.w);
    o1 = make_float4(mid.x + r7.x, mid.y + r7.y, mid.z + r7.z, mid.w + r7.w);
}

// 15-tap horizontal max for 4 adjacent outputs from 18 consecutive values
__device__ __forceinline__ float4 hmax15(float4 A, float4 B, float4 C, float4 D, float4 E) {
    float common = fmaxf(fmaxf(fmaxf(fmaxf(A.w, B.x), fmaxf(B.y, B.z)), B.w),
                   fmaxf(fmaxf(fmaxf(C.x, C.y), fmaxf(C.z, C.w)),
                         fmaxf(D.x, fmaxf(D.y, D.z))));            // v3..v14
    float4 r;
    r.x = fmaxf(common, fmaxf(fmaxf(A.x, A.y), A.z));              // v0..v14
    r.y = fmaxf(common, fmaxf(fmaxf(A.y, A.z), D.w));              // v1..v15
    r.z = fmaxf(common, fmaxf(fmaxf(A.z, D.w), E.x));              // v2..v16
    r.w = fmaxf(common, fmaxf(fmaxf(D.w, E.x), E.y));              // v3..v17
    return r;
}

// ---------------- fused response kernel: 32 wide x 64 tall output tile ----------------
// Smem arena (floats):
//   S   @ [0, 2880)      72x40 quantized image tile (dead after phase 1.5)
//   VB  @ [2880, 5680)   70x40 vertical [1,2,1] blur   (row r <-> product row Y0-3+r)
//   VD  @ [5680, 8480)   70x40 vertical [-1,0,1] diff
//   Hxx @ [0, 2240)      70x32 (reuses dead S)
//   Hyy @ [8480, 10720)
//   Hxy @ [10720, 12960)
#define CR_SMEM_FLOATS 12960
__global__ void __launch_bounds__(256) computeR(const float* __restrict__ img) {
    const int b  = blockIdx.z;
    const int X0 = blockIdx.x * 32;
    const int Y0 = blockIdx.y * 64;

    extern __shared__ __align__(16) float buf[];
    float (*S)[40]   = (float(*)[40])(buf);
    float (*VB)[40]  = (float(*)[40])(buf + 2880);
    float (*VD)[40]  = (float(*)[40])(buf + 5680);
    float (*Hxx)[32] = (float(*)[32])(buf);
    float (*Hyy)[32] = (float(*)[32])(buf + 8480);
    float (*Hxy)[32] = (float(*)[32])(buf + 10720);
    __shared__ float warpMax[8];

    const float* im = img + (size_t)b * HW;
    const int tid = threadIdx.x;
    const bool interior = (blockIdx.x > 0) & (blockIdx.x < 31) &
                          (blockIdx.y > 0) & (blockIdx.y < 15);

    // phase 1: load + quantize image with 4-halo (72x40)
    if (interior) {
        const float* p0 = im + (size_t)(Y0 - 4) * WID + (X0 - 4);
        for (int i = tid; i < 72 * 40; i += 256) {
            int r = i / 40, c = i - r * 40;
            float t = p0[r * WID + c];
            S[r][c] = fminf(fmaxf(floorf(t * 255.0f), 0.0f), 255.0f) / 255.0f;
        }
    } else {
        for (int i = tid; i < 72 * 40; i += 256) {
            int r = i / 40, c = i - r * 40;
            int gy = Y0 - 4 + r, gx = X0 - 4 + c;
            float v = 0.0f;
            if (gy >= 0 && gy < HGT && gx >= 0 && gx < WID) {
                float t = im[gy * WID + gx];
                v = fminf(fmaxf(floorf(t * 255.0f), 0.0f), 255.0f) / 255.0f;
            }
            S[r][c] = v;
        }
    }
    __syncthreads();

    // phase 1.5: separable sobel stage-1 (vertical blur + diff), 70 rows x 10 chunks
    for (int i = tid; i < 700; i += 256) {
        int r = i / 10, c0 = (i - r * 10) * 4;
        float4 x0 = ld4(&S[r][c0]);
        float4 x1 = ld4(&S[r + 1][c0]);
        float4 x2 = ld4(&S[r + 2][c0]);
        float4 vb, vd;
        vb.x = x0.x + 2.0f * x1.x + x2.x;  vd.x = x2.x - x0.x;
        vb.y = x0.y + 2.0f * x1.y + x2.y;  vd.y = x2.y - x0.y;
        vb.z = x0.z + 2.0f * x1.z + x2.z;  vd.z = x2.z - x0.z;
        vb.w = x0.w + 2.0f * x1.w + x2.w;  vd.w = x2.w - x0.w;
        st4(&VB[r][c0], vb);
        st4(&VD[r][c0], vd);
    }
    __syncthreads();

    // phase 2: ix/iy from VB/VD (1 sub / 2 fma each), products, horizontal 7-sum.
    // 70 rows x 8 chunks = 560 tasks. Writes Hxx over dead S (safe: barrier above).
    for (int i = tid; i < 560; i += 256) {
        int r = i >> 3, c0 = (i & 7) << 2;
        float4 B0 = ld4(&VB[r][c0]), B1 = ld4(&VB[r][c0 + 4]), B2 = ld4(&VB[r][c0 + 8]);
        float4 D0 = ld4(&VD[r][c0]), D1 = ld4(&VD[r][c0 + 4]), D2 = ld4(&VD[r][c0 + 8]);
        float bb[12] = {B0.x,B0.y,B0.z,B0.w, B1.x,B1.y,B1.z,B1.w, B2.x,B2.y,B2.z,B2.w};
        float dd[12] = {D0.x,D0.y,D0.z,D0.w, D1.x,D1.y,D1.z,D1.w, D2.x,D2.y,D2.z,D2.w};
        float ix[10], iy[10];
#pragma unroll
        for (int j = 0; j < 10; j++) {
            ix[j] = bb[j + 2] - bb[j];
            iy[j] = dd[j] + 2.0f * dd[j + 1] + dd[j + 2];
        }
        if (!interior) {
            int py = Y0 - 3 + r;
            float rowOK = (py >= 0 && py < HGT) ? 1.0f : 0.0f;
#pragma unroll
            for (int j = 0; j < 10; j++) {
                int gx = X0 + c0 - 3 + j;
                float m = (gx >= 0 && gx < WID) ? rowOK : 0.0f;
                ix[j] *= m; iy[j] *= m;
            }
        }
        float p[10];
#pragma unroll
        for (int j = 0; j < 10; j++) p[j] = ix[j] * ix[j];
        st4(&Hxx[r][c0], hsum7arr(p));
#pragma unroll
        for (int j = 0; j < 10; j++) p[j] = iy[j] * iy[j];
        st4(&Hyy[r][c0], hsum7arr(p));
#pragma unroll
        for (int j = 0; j < 10; j++) p[j] = ix[j] * iy[j];
        st4(&Hxy[r][c0], hsum7arr(p));
    }
    __syncthreads();

    // phase 3: vertical 7-sum for 2 consecutive rows per thread (tensors sequential)
    float localMax = 0.0f;
    {
        int c0 = (tid & 7) << 2, ly = (tid >> 3) << 1;
        float4 sxx0, sxx1, syy0, syy1, sxy0, sxy1;
        vsum7pair(Hxx, ly, c0, sxx0, sxx1);
        vsum7pair(Hyy, ly, c0, syy0, syy1);
        vsum7pair(Hxy, ly, c0, sxy0, sxy1);
#pragma unroll
        for (int o = 0; o < 2; o++) {
            float4 sxx = o ? sxx1 : sxx0;
            float4 syy = o ? syy1 : syy0;
            float4 sxy = o ? sxy1 : sxy0;
            float4 R;
            float ht = 0.5f * (sxx.x + syy.x), dd = 0.5f * (sxx.x - syy.x);
            R.x = ht - sqrtf(dd * dd + sxy.x * sxy.x);
            ht = 0.5f * (sxx.y + syy.y); dd = 0.5f * (sxx.y - syy.y);
            R.y = ht - sqrtf(dd * dd + sxy.y * sxy.y);
            ht = 0.5f * (sxx.z + syy.z); dd = 0.5f * (sxx.z - syy.z);
            R.z = ht - sqrtf(dd * dd + sxy.z * sxy.z);
            ht = 0.5f * (sxx.w + syy.w); dd = 0.5f * (sxx.w - syy.w);
            R.w = ht - sqrtf(dd * dd + sxy.w * sxy.w);
            *(float4*)&g_R[((size_t)b << 20) + (size_t)(Y0 + ly + o) * WID + (X0 + c0)] = R;
            localMax = fmaxf(localMax, fmaxf(fmaxf(R.x, R.y), fmaxf(R.z, R.w)));
        }
    }

#pragma unroll
    for (int o = 16; o > 0; o >>= 1)
        localMax = fmaxf(localMax, __shfl_xor_sync(0xffffffffu, localMax, o));
    if ((tid & 31) == 0) warpMax[tid >> 5] = localMax;
    __syncthreads();
    if (tid == 0) {
        float m = warpMax[0];
#pragma unroll
        for (int i = 1; i < 8; i++) m = fmaxf(m, warpMax[i]);
        atomicMax(&g_RmaxBits[b], __float_as_int(m));
    }
}

// ---------------- fused 15x15 NMS + threshold + collect: 32x64 tile ----------------
__global__ void __launch_bounds__(256) nmsCollect() {
    const int b  = blockIdx.z;
    const int X0 = blockIdx.x * 32;
    const int Y0 = blockIdx.y * 64;

    __shared__ __align__(16) float sh[78][48];   // gy=Y0-7+r, gx=X0-7+c
    __shared__ __align__(16) float hm[78][32];
    __shared__ float shThr;
    const int tid = threadIdx.x;
    const float* Rb = g_R + ((size_t)b << 20);
    const bool interior = (blockIdx.x > 0) & (blockIdx.x < 31) &
                          (blockIdx.y > 0) & (blockIdx.y < 15);

    if (interior) {
        const float* p0 = Rb + (size_t)(Y0 - 7) * WID + (X0 - 7);
        for (int i = tid; i < 78 * 48; i += 256) {
            int r = i / 48, c = i - r * 48;
            sh[r][c] = (c < 46) ? p0[r * WID + c] : NEG_INF;
        }
    } else {
        for (int i = tid; i < 78 * 48; i += 256) {
            int r = i / 48, c = i - r * 48;
            int gy = Y0 - 7 + r, gx = X0 - 7 + c;
            sh[r][c] = (c < 46 && gy >= 0 && gy < HGT && gx >= 0 && gx < WID)
                       ? Rb[(size_t)gy * WID + gx] : NEG_INF;
        }
    }
    if (tid == 0) shThr = 0.3f * __int_as_float(g_RmaxBits[b]);
    __syncthreads();

    // horizontal 15-max: 78 rows x 8 chunks
    for (int i = tid; i < 624; i += 256) {
        int r = i >> 3, c0 = (i & 7) << 2;
        st4(&hm[r][c0], hmax15(ld4(&sh[r][c0]),      ld4(&sh[r][c0 + 4]),
                               ld4(&sh[r][c0 + 8]),  ld4(&sh[r][c0 + 12]),
                               ld4(&sh[r][c0 + 16])));
    }
    __syncthreads();

    // vertical 15-max for 2 consecutive rows per thread (shared 14-row mid)
    const float thr = shThr;
    {
        int c0 = (tid & 7) << 2, ly = (tid >> 3) << 1;
        float4 row0 = ld4(&hm[ly][c0]);
        float4 mid  = ld4(&hm[ly + 1][c0]);
#pragma unroll
        for (int k = 2; k < 15; k++) {
            float4 t = ld4(&hm[ly + k][c0]);
            mid.x = fmaxf(mid.x, t.x); mid.y = fmaxf(mid.y, t.y);
            mid.z = fmaxf(mid.z, t.z); mid.w = fmaxf(mid.w, t.w);
        }
        float4 row15 = ld4(&hm[ly + 15][c0]);
        float pool[2][4] = {
            { fmaxf(mid.x, row0.x),  fmaxf(mid.y, row0.y),
              fmaxf(mid.z, row0.z),  fmaxf(mid.w, row0.w) },
            { fmaxf(mid.x, row15.x), fmaxf(mid.y, row15.y),
              fmaxf(mid.z, row15.z), fmaxf(mid.w, row15.w) } };
#pragma unroll
        for (int o = 0; o < 2; o++) {
            int y = Y0 + ly + o;
            const float* cenRow = &sh[ly + o + 7][c0 + 7];
#pragma unroll
            for (int j = 0; j < 4; j++) {
                float rv = cenRow[j];
                if (rv >= pool[o][j] && rv >= thr) {
                    unsigned int idx = (unsigned int)(y * WID + (X0 + c0 + j));
                    int pos = atomicAdd(&g_count[b], 1);
                    if (pos < CAP)
                        g_candKey[b][pos] = ((unsigned long long)__float_as_uint(rv) << 32)
                                          | (unsigned long long)(0xFFFFFFFFu - idx);
                }
            }
        }
    }
}

// ---------------- exact per-image top-K: MSD radix select, warp-shuffle scan ----------------
__global__ void __launch_bounds__(512) selectK(float* __restrict__ out, const int* __restrict__ topkPtr) {
    const int b   = blockIdx.x;
    const int tid = threadIdx.x;
    const int topK = *topkPtr;
    int n = g_count[b]; if (n > CAP) n = CAP;

    __shared__ int hist[256];
    __shared__ int warpSum[8];
    __shared__ unsigned long long shK;
    __shared__ int shRem, shDone;

    if (tid == 0) { shK = 0ull; shRem = topK; shDone = (n <= topK) ? 1 : 0; }
    __syncthreads();

    for (int byte = 7; byte >= 0; byte--) {
        if (shDone) break;
        if (tid < 256) hist[tid] = 0;
        __syncthreads();
        const unsigned long long pref = shK;
        const int shift = byte * 8;
        for (int i = tid; i < n; i += 512) {
            unsigned long long key = g_candKey[b][i];
            bool match = (byte == 7) || ((key >> (shift + 8)) == (pref >> (shift + 8)));
            if (match) atomicAdd(&hist[(int)((key >> shift) & 255)], 1);
        }
        __syncthreads();
        int h = 0, v = 0;
        if (tid < 256) {
            h = hist[tid];
            v = h;
            int lane = tid & 31;
#pragma unroll
            for (int off = 1; off < 32; off <<= 1) {
                int t = __shfl_down_sync(0xffffffffu, v, off);
                if (lane + off < 32) v += t;
            }
            if (lane == 0) warpSum[tid >> 5] = v;
        }
        __syncthreads();
        if (tid < 256) {
            int add = 0;
            for (int w = (tid >> 5) + 1; w < 8; w++) add += warpSum[w];
            v += add;                       // inclusive suffix sum from bin tid
            int here = v, above = v - h;
            int rem = shRem;
            if (here >= rem && above < rem) {   // unique boundary bin
                int inBin = rem - above;
                int cnt   = h;
                shK = pref | ((unsigned long long)(unsigned int)tid << shift);
                if (inBin == cnt || byte == 0) shDone = 1;
                else shRem = inBin;
            }
        }
        __syncthreads();
    }

    const unsigned long long K = (n <= topK) ? 0ull : shK;
    for (int i = tid; i < n; i += 512) {
        unsigned long long key = g_candKey[b][i];
        if (key >= K) {
            unsigned int idx = 0xFFFFFFFFu - (unsigned int)(key & 0xFFFFFFFFull);
            out[((size_t)b << 20) + idx] = 1.0f;
        }
    }
}

// ---------------- launch ----------------
extern "C" void kernel_launch(void* const* d_in, const int* in_sizes, int n_in,
                              void* d_out, int out_size) {
    const float* img  = (const float*)d_in[0];
    const int*   topk = (const int*)d_in[1];
    float*       out  = (float*)d_out;

    cudaFuncSetAttribute(computeR, cudaFuncAttributeMaxDynamicSharedMemorySize,
                         CR_SMEM_FLOATS * (int)sizeof(float));

    cudaMemsetAsync(d_out, 0, (size_t)out_size * sizeof(float), 0);
    initK<<<1, 32>>>();
    computeR<<<dim3(32, 16, B_IMG), 256, CR_SMEM_FLOATS * sizeof(float)>>>(img);
    nmsCollect<<<dim3(32, 16, B_IMG), 256>>>();
    selectK<<<B_IMG, 512>>>(out, topk);
}